// round 16
// baseline (speedup 1.0000x reference)
#include <cuda_runtime.h>
#include <math.h>
#include <stdint.h>

#define BSZ   4
#define CCH   128
#define NPT   2000
#define KNNK  9
#define NHEAD 4
#define HD    32
#define BN_EPS 1e-5f

// ---------------- scratch ------------------------------------------------
__device__ float g_w1sb[2*CCH*CCH];
__device__ float g_wkv [2*CCH*CCH];
__device__ float g_bkv [2*CCH];
__device__ float g_gram[(size_t)BSZ*NPT*NPT];
__device__ float g_xx[BSZ*NPT];
__device__ int   g_idx[BSZ*NPT*KNNK];
__device__ float g_uv[BSZ*2*CCH*NPT];
__device__ float g_h [(size_t)BSZ*CCH*NPT*KNNK];
__device__ float g_agg[BSZ*CCH*NPT];
__device__ float g_q  [BSZ*CCH*NPT];
__device__ float g_kv [BSZ*2*CCH*NPT];
__device__ float g_add[BSZ*CCH*NPT];
__device__ float g_cat[BSZ*2*CCH*NPT];
__device__ float g_hc [BSZ*2*CCH*NPT];

// ---------------- tf32 helpers -------------------------------------------
__device__ __forceinline__ uint32_t f2tf32(float x){
    uint32_t r;
    asm("cvt.rna.tf32.f32 %0, %1;" : "=r"(r) : "f"(x));
    return r;
}
__device__ __forceinline__ void mma_tf32(float* d, const uint32_t* a, uint32_t b0, uint32_t b1){
    asm volatile(
        "mma.sync.aligned.m16n8k8.row.col.f32.tf32.tf32.f32 "
        "{%0,%1,%2,%3},{%4,%5,%6,%7},{%8,%9},{%0,%1,%2,%3};"
        : "+f"(d[0]), "+f"(d[1]), "+f"(d[2]), "+f"(d[3])
        : "r"(a[0]), "r"(a[1]), "r"(a[2]), "r"(a[3]), "r"(b0), "r"(b1));
}
__device__ __forceinline__ void cp_async16(uint32_t saddr, const float* g, bool pred){
    asm volatile("cp.async.cg.shared.global [%0], [%1], 16, %2;"
        :: "r"(saddr), "l"(g), "r"(pred ? 16 : 0));
}
__device__ __forceinline__ void split_tf32(float x, uint32_t& hi, uint32_t& lo){
    hi = f2tf32(x);
    lo = f2tf32(x - __uint_as_float(hi));
}

// ---------------- split-tf32 MMA GEMM, cp.async double-buffered (R11) --------
#define GM_TN 64
#define GA_LD 20
#define GB_LD 72

template<int NW>
__global__ void __launch_bounds__(NW*32) gemm_mma(
    const float* __restrict__ A, const float* __restrict__ B, float* __restrict__ Cm,
    int M, int Nc, int Kc, int lda, int ldb, int ldc,
    long long sA, long long sB, long long sC,
    const float* __restrict__ bias,
    const float* __restrict__ gamma, const float* __restrict__ beta,
    int relu,
    const float* __restrict__ resid, long long sR, int ldr)
{
    constexpr int TMT = NW*16;
    constexpr int NTH = NW*32;
    constexpr int AIT = (TMT*4)/NTH;
    constexpr int BIT = 256/NTH;

    int bz = blockIdx.z;
    A  += (long long)bz * sA;
    B  += (long long)bz * sB;
    Cm += (long long)bz * sC;
    if (resid) resid += (long long)bz * sR;

    __shared__ float As[2][TMT*GA_LD];
    __shared__ float Bs[2][16*GB_LD];

    int m0 = blockIdx.y * TMT;
    int n0 = blockIdx.x * GM_TN;
    int tid = threadIdx.x;
    int w = tid >> 5, lane = tid & 31;
    int g = lane >> 2, t = lane & 3;
    int row = w*16;

    int a_k4 = tid & 3,  a_r  = tid >> 2;
    int b_n4 = tid & 15, b_k  = tid >> 4;

    float acc[8][4];
    #pragma unroll
    for (int i=0;i<8;i++)
        #pragma unroll
        for (int j=0;j<4;j++) acc[i][j] = 0.f;

#define GMM_PREFETCH(KC, BUF) {                                              \
    _Pragma("unroll")                                                        \
    for (int it=0; it<AIT; it++){                                            \
        int r = a_r + it*(NTH/4);                                            \
        int gm = m0 + r;                                                     \
        uint32_t sa = (uint32_t)__cvta_generic_to_shared(                    \
            &As[BUF][r*GA_LD + a_k4*4]);                                     \
        cp_async16(sa, A + (long long)gm*lda + (KC) + a_k4*4, gm < M);       \
    }                                                                        \
    _Pragma("unroll")                                                        \
    for (int it=0; it<BIT; it++){                                            \
        int k_ = b_k + it*(NTH/16);                                          \
        int gn = n0 + b_n4*4;                                                \
        uint32_t sb = (uint32_t)__cvta_generic_to_shared(                    \
            &Bs[BUF][k_*GB_LD + b_n4*4]);                                    \
        cp_async16(sb, B + (long long)((KC) + k_)*ldb + gn, gn < Nc);        \
    }                                                                        \
    asm volatile("cp.async.commit_group;" ::: "memory"); }

#define GMM_COMPUTE(BUF) {                                                   \
    _Pragma("unroll")                                                        \
    for (int ks=0; ks<2; ks++){                                              \
        int c0 = ks*8;                                                       \
        uint32_t ah[4], al[4];                                               \
        {                                                                    \
            float a0 = As[BUF][(row+g  )*GA_LD + c0 + t];                    \
            float a1 = As[BUF][(row+8+g)*GA_LD + c0 + t];                    \
            float a2 = As[BUF][(row+g  )*GA_LD + c0 + t + 4];                \
            float a3 = As[BUF][(row+8+g)*GA_LD + c0 + t + 4];                \
            split_tf32(a0, ah[0], al[0]);                                    \
            split_tf32(a1, ah[1], al[1]);                                    \
            split_tf32(a2, ah[2], al[2]);                                    \
            split_tf32(a3, ah[3], al[3]);                                    \
        }                                                                    \
        int kr = ks*8 + t;                                                   \
        _Pragma("unroll")                                                    \
        for (int nt=0; nt<8; nt++){                                          \
            int cidx = nt*8 + g;                                             \
            float b0 = Bs[BUF][(kr  )*GB_LD + cidx];                         \
            float b1 = Bs[BUF][(kr+4)*GB_LD + cidx];                         \
            uint32_t bh0, bl0, bh1, bl1;                                     \
            split_tf32(b0, bh0, bl0);                                        \
            split_tf32(b1, bh1, bl1);                                        \
            mma_tf32(acc[nt], ah, bh0, bh1);                                 \
            mma_tf32(acc[nt], ah, bl0, bl1);                                 \
            mma_tf32(acc[nt], al, bh0, bh1);                                 \
        }                                                                    \
    } }

    const int NC = Kc >> 4;
    GMM_PREFETCH(0, 0);
    int buf = 0;
    for (int c = 0; c < NC; c++){
        if (c + 1 < NC){
            GMM_PREFETCH((c+1)*16, buf^1);
            asm volatile("cp.async.wait_group 1;" ::: "memory");
        } else {
            asm volatile("cp.async.wait_group 0;" ::: "memory");
        }
        __syncthreads();
        GMM_COMPUTE(buf);
        __syncthreads();
        buf ^= 1;
    }

    const float invs = rsqrtf(1.0f + BN_EPS);
    #pragma unroll
    for (int half=0; half<2; half++){
        int gm = m0 + row + half*8 + g;
        if (gm >= M) continue;
        float bi = bias  ? bias[gm]       : 0.f;
        float ga = gamma ? gamma[gm]*invs : 1.f;
        float be = beta  ? beta[gm]       : 0.f;
        #pragma unroll
        for (int nt=0; nt<8; nt++){
            int c0 = n0 + nt*8 + 2*t;
            #pragma unroll
            for (int jj=0; jj<2; jj++){
                int gn = c0 + jj;
                if (gn >= Nc) continue;
                float r = acc[nt][half*2 + jj] + bi;
                if (gamma) r = r*ga + be;
                if (relu)  r = fmaxf(r, 0.f);
                if (resid) r += resid[(long long)gm*ldr + gn];
                Cm[(long long)gm*ldc + gn] = r;
            }
        }
    }
#undef GMM_PREFETCH
#undef GMM_COMPUTE
}

// ---------------- conv2 + max-over-k fused (R13 proven) --------------------
#define C2_TN 72
#define C2_SLD 76
#define C2_NCOLS (NPT*KNNK)

__global__ void __launch_bounds__(256) conv2max_mma(
    const float* __restrict__ W,
    const float* __restrict__ hsrc,
    const float* __restrict__ bias, const float* __restrict__ gamma,
    const float* __restrict__ beta,
    float* __restrict__ agg,
    float* __restrict__ cat)
{
    __shared__ float SM[CCH*C2_SLD];
    float* ASb = SM;
    float* BSb = SM + 2*CCH*GA_LD;
#define C2_AS(BUF) (ASb + (BUF)*CCH*GA_LD)
#define C2_BS(BUF) (BSb + (BUF)*16*C2_TN)

    int b = blockIdx.z;
    const float* Bsrc = hsrc + (long long)b*CCH*C2_NCOLS;
    int n0 = blockIdx.x * C2_TN;
    int tid = threadIdx.x;
    int w = tid >> 5, lane = tid & 31;
    int g = lane >> 2, t = lane & 3;
    int row = w*16;
    int a_k4 = tid & 3, a_r = tid >> 2;

    float acc[9][4];
    #pragma unroll
    for (int i=0;i<9;i++)
        #pragma unroll
        for (int j=0;j<4;j++) acc[i][j] = 0.f;

#define C2_PREFETCH(KC, BUF) {                                               \
    _Pragma("unroll")                                                        \
    for (int it=0; it<2; it++){                                              \
        int r = a_r + it*64;                                                 \
        uint32_t sa = (uint32_t)__cvta_generic_to_shared(                    \
            &C2_AS(BUF)[r*GA_LD + a_k4*4]);                                  \
        cp_async16(sa, W + (long long)r*CCH + (KC) + a_k4*4, true);          \
    }                                                                        \
    _Pragma("unroll")                                                        \
    for (int it=0; it<2; it++){                                              \
        int e = tid + it*256;                                                \
        if (e < 288){                                                        \
            int k_ = e/18, n4 = e%18;                                        \
            uint32_t sb = (uint32_t)__cvta_generic_to_shared(                \
                &C2_BS(BUF)[k_*C2_TN + n4*4]);                               \
            cp_async16(sb, Bsrc + (long long)((KC)+k_)*C2_NCOLS + n0 + n4*4, true); \
        }                                                                    \
    }                                                                        \
    asm volatile("cp.async.commit_group;" ::: "memory"); }

#define C2_COMPUTE(BUF) {                                                    \
    _Pragma("unroll")                                                        \
    for (int ks=0; ks<2; ks++){                                              \
        int c0 = ks*8;                                                       \
        uint32_t ah[4], al[4];                                               \
        {                                                                    \
            float a0 = C2_AS(BUF)[(row+g  )*GA_LD + c0 + t];                 \
            float a1 = C2_AS(BUF)[(row+8+g)*GA_LD + c0 + t];                 \
            float a2 = C2_AS(BUF)[(row+g  )*GA_LD + c0 + t + 4];             \
            float a3 = C2_AS(BUF)[(row+8+g)*GA_LD + c0 + t + 4];             \
            split_tf32(a0, ah[0], al[0]);                                    \
            split_tf32(a1, ah[1], al[1]);                                    \
            split_tf32(a2, ah[2], al[2]);                                    \
            split_tf32(a3, ah[3], al[3]);                                    \
        }                                                                    \
        int kr = ks*8 + t;                                                   \
        _Pragma("unroll")                                                    \
        for (int nt=0; nt<9; nt++){                                          \
            int cidx = nt*8 + g;                                             \
            float b0 = C2_BS(BUF)[(kr  )*C2_TN + cidx];                      \
            float b1 = C2_BS(BUF)[(kr+4)*C2_TN + cidx];                      \
            uint32_t bh0, bl0, bh1, bl1;                                     \
            split_tf32(b0, bh0, bl0);                                        \
            split_tf32(b1, bh1, bl1);                                        \
            mma_tf32(acc[nt], ah, bh0, bh1);                                 \
            mma_tf32(acc[nt], ah, bl0, bl1);                                 \
            mma_tf32(acc[nt], al, bh0, bh1);                                 \
        }                                                                    \
    } }

    const int NC = CCH >> 4;
    C2_PREFETCH(0, 0);
    int buf = 0;
    for (int c = 0; c < NC; c++){
        if (c + 1 < NC){
            C2_PREFETCH((c+1)*16, buf^1);
            asm volatile("cp.async.wait_group 1;" ::: "memory");
        } else {
            asm volatile("cp.async.wait_group 0;" ::: "memory");
        }
        __syncthreads();
        C2_COMPUTE(buf);
        __syncthreads();
        buf ^= 1;
    }

    const float invs = rsqrtf(1.0f + BN_EPS);
    #pragma unroll
    for (int half=0; half<2; half++){
        int r = row + half*8 + g;
        float bi = bias[r];
        float ga = gamma[r]*invs;
        float be = beta[r];
        #pragma unroll
        for (int nt=0; nt<9; nt++){
            #pragma unroll
            for (int jj=0; jj<2; jj++){
                int c = nt*8 + 2*t + jj;
                float v = fmaxf((acc[nt][half*2 + jj] + bi)*ga + be, 0.f);
                SM[r*C2_SLD + c] = v;
            }
        }
    }
    __syncthreads();

    #pragma unroll
    for (int e = tid; e < CCH*8; e += 256){
        int r = e >> 3, gi = e & 7;
        int n = 8*blockIdx.x + gi;
        const float* p = &SM[r*C2_SLD + gi*9];
        float m = p[0];
        #pragma unroll
        for (int k=1;k<9;k++) m = fmaxf(m, p[k]);
        agg[((long long)b*CCH + r)*NPT + n] = m;
        cat[(long long)b*2*CCH*NPT + (long long)r*NPT + n] = m;
    }
#undef C2_PREFETCH
#undef C2_COMPUTE
#undef C2_AS
#undef C2_BS
}

// ---------------- Gram via split-tf32 MMA (R9 proven) ------------------------
#define GM_TM 128
#define GRA_LD 17

__global__ void __launch_bounds__(256) gram_mma(
    const float* __restrict__ x,
    float* __restrict__ gram,
    float* __restrict__ xx)
{
    __shared__ float AH[GM_TM*GRA_LD], AL[GM_TM*GRA_LD];
    __shared__ float BH[16*GB_LD],    BL[16*GB_LD];

    int b = blockIdx.z;
    const float* xb = x + (long long)b*CCH*NPT;
    float* gb = gram + (long long)b*NPT*NPT;

    int tt = blockIdx.x;
    int bi = 0;
    while ((32*(bi+1) - (bi+1)*bi) <= tt) bi++;
    int bj2 = 2*bi + (tt - (32*bi - bi*(bi-1)));

    int m0 = bi * GM_TM;
    int n0 = bj2 * GM_TN;
    int tid = threadIdx.x;
    int w = tid >> 5, lane = tid & 31;
    int g = lane >> 2, t = lane & 3;
    int row = w*16;

    float acc[8][4];
    #pragma unroll
    for (int i=0;i<8;i++)
        #pragma unroll
        for (int j=0;j<4;j++) acc[i][j] = 0.f;

    for (int kc = 0; kc < CCH; kc += 16) {
        #pragma unroll
        for (int it=0; it<8; it++){
            int e = tid + it*256;
            int r = e & 127, kk = e >> 7;
            int gm = m0 + r;
            float av = (gm < NPT) ? xb[(long long)(kc+kk)*NPT + gm] : 0.f;
            float ah = __uint_as_float(f2tf32(av));
            AH[r*GRA_LD + kk] = ah;
            AL[r*GRA_LD + kk] = __uint_as_float(f2tf32(av - ah));
        }
        #pragma unroll
        for (int it=0; it<4; it++){
            int e = tid + it*256;
            int n_ = e & 63, k_ = e >> 6;
            int gn = n0 + n_;
            float bv = (gn < NPT) ? xb[(long long)(kc + k_)*NPT + gn] : 0.f;
            float bh = __uint_as_float(f2tf32(bv));
            BH[k_*GB_LD + n_] = bh;
            BL[k_*GB_LD + n_] = __uint_as_float(f2tf32(bv - bh));
        }
        __syncthreads();

        #pragma unroll
        for (int ks=0; ks<2; ks++){
            int c0 = ks*8;
            uint32_t ah[4], al[4];
            ah[0] = __float_as_uint(AH[(row+g  )*GRA_LD + c0 + t]);
            ah[1] = __float_as_uint(AH[(row+8+g)*GRA_LD + c0 + t]);
            ah[2] = __float_as_uint(AH[(row+g  )*GRA_LD + c0 + t + 4]);
            ah[3] = __float_as_uint(AH[(row+8+g)*GRA_LD + c0 + t + 4]);
            al[0] = __float_as_uint(AL[(row+g  )*GRA_LD + c0 + t]);
            al[1] = __float_as_uint(AL[(row+8+g)*GRA_LD + c0 + t]);
            al[2] = __float_as_uint(AL[(row+g  )*GRA_LD + c0 + t + 4]);
            al[3] = __float_as_uint(AL[(row+8+g)*GRA_LD + c0 + t + 4]);
            int kr = ks*8 + t;
            #pragma unroll
            for (int nt=0; nt<8; nt++){
                int cidx = nt*8 + g;
                uint32_t bh0 = __float_as_uint(BH[(kr  )*GB_LD + cidx]);
                uint32_t bh1 = __float_as_uint(BH[(kr+4)*GB_LD + cidx]);
                uint32_t bl0 = __float_as_uint(BL[(kr  )*GB_LD + cidx]);
                uint32_t bl1 = __float_as_uint(BL[(kr+4)*GB_LD + cidx]);
                mma_tf32(acc[nt], ah, bh0, bh1);
                mma_tf32(acc[nt], ah, bl0, bl1);
                mma_tf32(acc[nt], al, bh0, bh1);
            }
        }
        __syncthreads();
    }

    bool diagtile = (bj2 >> 1) == bi;
    #pragma unroll
    for (int half=0; half<2; half++){
        int gm = m0 + row + half*8 + g;
        if (gm >= NPT) continue;
        #pragma unroll
        for (int nt=0; nt<8; nt++){
            #pragma unroll
            for (int jj=0; jj<2; jj++){
                int gn = n0 + nt*8 + 2*t + jj;
                if (gn >= NPT) continue;
                float val = acc[nt][half*2 + jj];
                gb[(long long)gm*NPT + gn] = val;
                gb[(long long)gn*NPT + gm] = val;
                if (diagtile && gm == gn) xx[b*NPT + gm] = val;
            }
        }
    }
}

// ---------------- prep ------------------------------------------------------
__global__ void prep_kernel(const float* __restrict__ w1,
                            const float* __restrict__ wk, const float* __restrict__ wv,
                            const float* __restrict__ bk, const float* __restrict__ bv,
                            float* __restrict__ w1sb, float* __restrict__ wkv,
                            float* __restrict__ bkv)
{
    int i = blockIdx.x*blockDim.x + threadIdx.x;
    if (i < CCH*CCH) {
        int o = i / CCH, c = i % CCH;
        float a  = w1[o*2*CCH + c];
        float bb = w1[o*2*CCH + CCH + c];
        w1sb[i] = a + bb;
        w1sb[CCH*CCH + i] = bb;
        wkv[i] = wk[i];
        wkv[CCH*CCH + i] = wv[i];
    }
    if (i < 2*CCH) bkv[i] = (i < CCH) ? bk[i] : bv[i - CCH];
}

// ---------------- topk: lane sort-8 + warp k-way merge -----------------------
__global__ void __launch_bounds__(256) topk_kernel(const float* __restrict__ gram,
                                                   const float* __restrict__ xx,
                                                   int* __restrict__ idx)
{
    int n = blockIdx.x, b = blockIdx.y;
    const float* row = gram + ((long long)(b*NPT+n))*NPT;
    const float* xb  = xx + b*NPT;
    int tid = threadIdx.x, w = tid >> 5, l = tid & 31;

    float v[8]; int id[8];
    #pragma unroll
    for (int j=0;j<8;j++){
        int m = w*256 + j*32 + l;
        bool ok = m < NPT;
        v[j]  = ok ? (2.f*row[m] - xb[m]) : -INFINITY;
        id[j] = ok ? m : 0x7fffffff;
    }
#define CSWP(a,bb) { bool sw = (v[a]<v[bb]) || (v[a]==v[bb] && id[a]>id[bb]); \
    float tv = sw?v[bb]:v[a]; float uv2 = sw?v[a]:v[bb]; v[a]=tv; v[bb]=uv2;   \
    int ti = sw?id[bb]:id[a]; int ui = sw?id[a]:id[bb]; id[a]=ti; id[bb]=ui; }
    CSWP(0,1) CSWP(2,3) CSWP(4,5) CSWP(6,7)
    CSWP(0,2) CSWP(1,3) CSWP(4,6) CSWP(5,7)
    CSWP(1,2) CSWP(5,6)
    CSWP(0,4) CSWP(1,5) CSWP(2,6) CSWP(3,7)
    CSWP(2,4) CSWP(3,5)
    CSWP(1,2) CSWP(3,4) CSWP(5,6)
#undef CSWP

    __shared__ float wv[8][12];
    __shared__ int   wi[8][12];

    float hv = v[0]; int hi = id[0];
    #pragma unroll
    for (int t=0;t<KNNK;t++){
        float bvv = hv; int bii = hi;
        #pragma unroll
        for (int s=16; s>0; s>>=1){
            float ov = __shfl_xor_sync(0xffffffffu, bvv, s);
            int   oi = __shfl_xor_sync(0xffffffffu, bii, s);
            if (ov > bvv || (ov == bvv && oi < bii)) { bvv = ov; bii = oi; }
        }
        if (l == 0) { wv[w][t] = bvv; wi[w][t] = bii; }
        if (hi == bii) {
            #pragma unroll
            for (int j=0;j<7;j++){ v[j]=v[j+1]; id[j]=id[j+1]; }
            v[7] = -INFINITY; id[7] = 0x7fffffff;
            hv = v[0]; hi = id[0];
        }
    }
    __syncthreads();

    if (w == 0){
        int ptr = 0;
        float hv2 = (l < 8) ? wv[l][0] : -INFINITY;
        int   hi2 = (l < 8) ? wi[l][0] : 0x7fffffff;
        int* outp = idx + (b*NPT+n)*KNNK;
        #pragma unroll
        for (int t=0;t<KNNK;t++){
            float bvv = hv2; int bii = hi2;
            #pragma unroll
            for (int s=16; s>0; s>>=1){
                float ov = __shfl_xor_sync(0xffffffffu, bvv, s);
                int   oi = __shfl_xor_sync(0xffffffffu, bii, s);
                if (ov > bvv || (ov == bvv && oi < bii)) { bvv = ov; bii = oi; }
            }
            if (l == 0) outp[t] = bii;
            if (hi2 == bii){
                ptr++;
                hv2 = (ptr < KNNK && l < 8) ? wv[l][ptr] : -INFINITY;
                hi2 = (ptr < KNNK && l < 8) ? wi[l][ptr] : 0x7fffffff;
            }
        }
    }
}

// h[b,c,n*9+k] = relu( bn( u[b,c,n] - v[b,c,idx] + b1[c] ) )
__global__ void gather_h_kernel(const float* __restrict__ uv,
                                const int* __restrict__ idx,
                                const float* __restrict__ b1, const float* __restrict__ g1,
                                const float* __restrict__ be1, float* __restrict__ h)
{
    long long i = (long long)blockIdx.x*blockDim.x + threadIdx.x;
    const long long total = (long long)BSZ*CCH*NPT*KNNK;
    if (i >= total) return;
    int k = (int)(i % KNNK);
    long long r = i / KNNK;
    int n = (int)(r % NPT); r /= NPT;
    int c = (int)(r % CCH);
    int b = (int)(r / CCH);
    int j = idx[(b*NPT+n)*KNNK + k];
    const float* ub = uv + (long long)b*2*CCH*NPT + (long long)c*NPT;
    float uvv = ub[n];
    float vg  = ub[(long long)CCH*NPT + j];
    const float invs = rsqrtf(1.f + BN_EPS);
    float val = (uvv - vg + b1[c]) * (g1[c]*invs) + be1[c];
    h[((long long)(b*CCH+c))*NPT*KNNK + (long long)n*KNNK + k] = fmaxf(val, 0.f);
}

// ---------------- flash attention, tf32 mma + cp.async K/V pipeline ----------
#define FQT 128
#define FKT 64
#define QS_LD 36
#define KD_LD 72
#define VR_LD 76
#define OF_QH 0
#define OF_QL (FQT*QS_LD)
#define OF_KRAW (OF_QL + FQT*QS_LD)
#define KBUF (HD*KD_LD)
#define OF_VRAW (OF_KRAW + 2*KBUF)
#define VBUF (HD*VR_LD)
#define FLASH_SM_FLOATS (OF_VRAW + 2*VBUF)

__global__ void __launch_bounds__(256,2) flash_mma(
    const float* __restrict__ q,
    const float* __restrict__ kv,
    float* __restrict__ add)
{
    extern __shared__ float sm[];
    float* Qsh = sm + OF_QH;
    float* Qsl = sm + OF_QL;

    int n0 = blockIdx.x * FQT;
    int h  = blockIdx.y;
    int b  = blockIdx.z;
    const float* qp = q  + ((long long)b*CCH   + h*HD)*NPT;
    const float* kp = kv + ((long long)b*2*CCH + h*HD)*NPT;
    const float* vp = kv + ((long long)b*2*CCH + CCH + h*HD)*NPT;
    float* oh = add + ((long long)b*CCH + h*HD)*NPT;

    int tid = threadIdx.x;
    const float scale = 0.17677669529663689f;

    // K/V tile prefetch: 32 rows x 16 vec4 each; zero-fill OOB via pred.
#define FL_PREFETCH(TI, BUF) {                                               \
    int m0p = (TI)*FKT;                                                      \
    _Pragma("unroll")                                                        \
    for (int it=0; it<2; it++){                                              \
        int e = tid + it*256;                                                \
        int d = e >> 4, n4 = e & 15;                                         \
        int gn = m0p + n4*4;                                                 \
        bool ok = (gn + 3) < NPT;                                            \
        uint32_t sk = (uint32_t)__cvta_generic_to_shared(                    \
            sm + OF_KRAW + (BUF)*KBUF + d*KD_LD + n4*4);                     \
        cp_async16(sk, kp + (long long)d*NPT + gn, ok);                      \
        uint32_t sv = (uint32_t)__cvta_generic_to_shared(                    \
            sm + OF_VRAW + (BUF)*VBUF + d*VR_LD + n4*4);                     \
        cp_async16(sv, vp + (long long)d*NPT + gn, ok);                      \
    }                                                                        \
    asm volatile("cp.async.commit_group;" ::: "memory"); }

    FL_PREFETCH(0, 0);

    #pragma unroll
    for (int e = tid; e < FQT*HD; e += 256) {
        int d = e >> 7, r = e & 127;
        int n = n0 + r;
        float qv = (n < NPT) ? qp[d*NPT + n]*scale : 0.f;
        float hf = __uint_as_float(f2tf32(qv));
        Qsh[r*QS_LD + d] = hf;
        Qsl[r*QS_LD + d] = __uint_as_float(f2tf32(qv - hf));
    }

    int w = tid >> 5, lane = tid & 31;
    int g = lane >> 2, t = lane & 3;
    int row = w*16 + g;

    float O[4][4];
    #pragma unroll
    for (int i=0;i<4;i++)
        #pragma unroll
        for (int j=0;j<4;j++) O[i][j] = 0.f;
    float m0r = -INFINITY, m1r = -INFINITY, l0r = 0.f, l1r = 0.f;

    const int NT = (NPT + FKT - 1)/FKT;
    int buf = 0;

    for (int ti = 0; ti < NT; ti++) {
        int m0 = ti*FKT;
        if (ti + 1 < NT){
            FL_PREFETCH(ti+1, buf^1);
            asm volatile("cp.async.wait_group 1;" ::: "memory");
        } else {
            asm volatile("cp.async.wait_group 0;" ::: "memory");
        }
        __syncthreads();

        const float* Kr = sm + OF_KRAW + buf*KBUF;
        const float* Vr = sm + OF_VRAW + buf*VBUF;

        uint32_t qa[4][4], ql[4][4];
        #pragma unroll
        for (int ks=0; ks<4; ks++){
            int c0 = ks*8;
            qa[ks][0] = __float_as_uint(Qsh[(row  )*QS_LD + c0 + t]);
            qa[ks][1] = __float_as_uint(Qsh[(row+8)*QS_LD + c0 + t]);
            qa[ks][2] = __float_as_uint(Qsh[(row  )*QS_LD + c0 + t + 4]);
            qa[ks][3] = __float_as_uint(Qsh[(row+8)*QS_LD + c0 + t + 4]);
            ql[ks][0] = __float_as_uint(Qsl[(row  )*QS_LD + c0 + t]);
            ql[ks][1] = __float_as_uint(Qsl[(row+8)*QS_LD + c0 + t]);
            ql[ks][2] = __float_as_uint(Qsl[(row  )*QS_LD + c0 + t + 4]);
            ql[ks][3] = __float_as_uint(Qsl[(row+8)*QS_LD + c0 + t + 4]);
        }

        float S[8][4];
        #pragma unroll
        for (int nt=0; nt<8; nt++){
            S[nt][0]=0.f; S[nt][1]=0.f; S[nt][2]=0.f; S[nt][3]=0.f;
            #pragma unroll
            for (int ks=0; ks<4; ks++){
                int kr = ks*8 + t;
                int cidx = nt*8 + g;
                float k0 = Kr[(kr  )*KD_LD + cidx];
                float k1 = Kr[(kr+4)*KD_LD + cidx];
                uint32_t bh0, bl0, bh1, bl1;
                split_tf32(k0, bh0, bl0);
                split_tf32(k1, bh1, bl1);
                mma_tf32(S[nt], qa[ks], bh0, bh1);
                mma_tf32(S[nt], qa[ks], bl0, bl1);
                mma_tf32(S[nt], ql[ks], bh0, bh1);
            }
        }

        int mval = NPT - m0;
        float lm0 = -INFINITY, lm1 = -INFINITY;
        #pragma unroll
        for (int nt=0; nt<8; nt++){
            int c0 = nt*8 + 2*t, c1 = c0 + 1;
            if (c0 < mval){ lm0 = fmaxf(lm0, S[nt][0]); lm1 = fmaxf(lm1, S[nt][2]); }
            if (c1 < mval){ lm0 = fmaxf(lm0, S[nt][1]); lm1 = fmaxf(lm1, S[nt][3]); }
        }
        lm0 = fmaxf(lm0, __shfl_xor_sync(0xffffffffu, lm0, 1));
        lm0 = fmaxf(lm0, __shfl_xor_sync(0xffffffffu, lm0, 2));
        lm1 = fmaxf(lm1, __shfl_xor_sync(0xffffffffu, lm1, 1));
        lm1 = fmaxf(lm1, __shfl_xor_sync(0xffffffffu, lm1, 2));

        float mn0 = fmaxf(m0r, lm0), mn1 = fmaxf(m1r, lm1);
        float al0 = __expf(m0r - mn0), al1 = __expf(m1r - mn1);
        m0r = mn0; m1r = mn1;

        float ls0 = 0.f, ls1 = 0.f;
        #pragma unroll
        for (int nt=0; nt<8; nt++){
            int c0 = nt*8 + 2*t, c1 = c0 + 1;
            float e0 = (c0 < mval) ? __expf(S[nt][0] - mn0) : 0.f;
            float e1 = (c1 < mval) ? __expf(S[nt][1] - mn0) : 0.f;
            float e2 = (c0 < mval) ? __expf(S[nt][2] - mn1) : 0.f;
            float e3 = (c1 < mval) ? __expf(S[nt][3] - mn1) : 0.f;
            S[nt][0]=e0; S[nt][1]=e1; S[nt][2]=e2; S[nt][3]=e3;
            ls0 += e0 + e1; ls1 += e2 + e3;
        }
        ls0 += __shfl_xor_sync(0xffffffffu, ls0, 1);
        ls0 += __shfl_xor_sync(0xffffffffu, ls0, 2);
        ls1 += __shfl_xor_sync(0xffffffffu, ls1, 1);
        ls1 += __shfl_xor_sync(0xffffffffu, ls1, 2);
        l0r = l0r*al0 + ls0;
        l1r = l1r*al1 + ls1;
        #pragma unroll
        for (int nd=0; nd<4; nd++){
            O[nd][0] *= al0; O[nd][1] *= al0;
            O[nd][2] *= al1; O[nd][3] *= al1;
        }

        int s1 = g*4 + (t>>1), s2 = s1 + 2;
        bool odd = (t & 1);
        #pragma unroll
        for (int kt2=0; kt2<8; kt2++){
            float x0 = __shfl_sync(0xffffffffu, S[kt2][0], s1);
            float x1 = __shfl_sync(0xffffffffu, S[kt2][1], s1);
            float x2 = __shfl_sync(0xffffffffu, S[kt2][2], s1);
            float x3 = __shfl_sync(0xffffffffu, S[kt2][3], s1);
            float y0 = __shfl_sync(0xffffffffu, S[kt2][0], s2);
            float y1 = __shfl_sync(0xffffffffu, S[kt2][1], s2);
            float y2 = __shfl_sync(0xffffffffu, S[kt2][2], s2);
            float y3 = __shfl_sync(0xffffffffu, S[kt2][3], s2);
            uint32_t pa[4];
            pa[0] = f2tf32(odd ? x1 : x0);
            pa[1] = f2tf32(odd ? x3 : x2);
            pa[2] = f2tf32(odd ? y1 : y0);
            pa[3] = f2tf32(odd ? y3 : y2);
            #pragma unroll
            for (int nd=0; nd<4; nd++){
                uint32_t b0 = f2tf32(Vr[(nd*8+g)*VR_LD + kt2*8 + t    ]);
                uint32_t b1 = f2tf32(Vr[(nd*8+g)*VR_LD + kt2*8 + t + 4]);
                mma_tf32(O[nd], pa, b0, b1);
            }
        }
        __syncthreads();
        buf ^= 1;
    }

    float inv0 = 1.f / l0r, inv1 = 1.f / l1r;
    int q0 = n0 + row, q1 = q0 + 8;
    #pragma unroll
    for (int nd=0; nd<4; nd++){
        int d0 = nd*8 + 2*t, d1 = d0 + 1;
        if (q0 < NPT){
            oh[(long long)d0*NPT + q0] = O[nd][0]*inv0;
            oh[(long long)d1*NPT + q0] = O[nd][1]*inv0;
        }
        if (q1 < NPT){
            oh[(long long)d0*NPT + q1] = O[nd][2]*inv1;
            oh[(long long)d1*NPT + q1] = O[nd][3]*inv1;
        }
    }
#undef FL_PREFETCH
}

// ---------------- launch ------------------------------------------------------
static inline dim3 gmma64(int M, int Nc, int batches) {
    return dim3((Nc + GM_TN - 1)/GM_TN, (M + 63)/64, batches);
}

extern "C" void kernel_launch(void* const* d_in, const int* in_sizes, int n_in,
                              void* d_out, int out_size)
{
    const float* x    = (const float*)d_in[0];
    const float* y    = (const float*)d_in[1];
    const float* dgw1 = (const float*)d_in[2];
    const float* dgb1 = (const float*)d_in[3];
    const float* dgg1 = (const float*)d_in[4];
    const float* dgbe1= (const float*)d_in[5];
    const float* dgw2 = (const float*)d_in[6];
    const float* dgb2 = (const float*)d_in[7];
    const float* dgg2 = (const float*)d_in[8];
    const float* dgbe2= (const float*)d_in[9];
    const float* wq   = (const float*)d_in[10];
    const float* bq   = (const float*)d_in[11];
    const float* wk   = (const float*)d_in[12];
    const float* bk   = (const float*)d_in[13];
    const float* wv   = (const float*)d_in[14];
    const float* bv   = (const float*)d_in[15];
    const float* wmh  = (const float*)d_in[16];
    const float* bmh  = (const float*)d_in[17];
    const float* wc1  = (const float*)d_in[18];
    const float* bc1  = (const float*)d_in[19];
    const float* cg   = (const float*)d_in[20];
    const float* cbe  = (const float*)d_in[21];
    const float* wc2  = (const float*)d_in[22];
    const float* bc2  = (const float*)d_in[23];
    float* out = (float*)d_out;

    float *w1sb,*wkv,*bkv,*gram,*xx,*uv,*h,*agg,*q,*kvb,*add,*cat,*hc;
    int* idx;
    cudaGetSymbolAddress((void**)&w1sb, g_w1sb);
    cudaGetSymbolAddress((void**)&wkv,  g_wkv);
    cudaGetSymbolAddress((void**)&bkv,  g_bkv);
    cudaGetSymbolAddress((void**)&gram, g_gram);
    cudaGetSymbolAddress((void**)&xx,   g_xx);
    cudaGetSymbolAddress((void**)&idx,  g_idx);
    cudaGetSymbolAddress((void**)&uv,   g_uv);
    cudaGetSymbolAddress((void**)&h,    g_h);
    cudaGetSymbolAddress((void**)&agg,  g_agg);
    cudaGetSymbolAddress((void**)&q,    g_q);
    cudaGetSymbolAddress((void**)&kvb,  g_kv);
    cudaGetSymbolAddress((void**)&add,  g_add);
    cudaGetSymbolAddress((void**)&cat,  g_cat);
    cudaGetSymbolAddress((void**)&hc,   g_hc);

    const long long CN  = (long long)CCH*NPT;
    const long long CNK = (long long)CCH*NPT*KNNK;
    const int FLASH_SMEM = FLASH_SM_FLOATS * 4;
    const int NTRI2 = 272;

    cudaFuncSetAttribute(flash_mma, cudaFuncAttributeMaxDynamicSharedMemorySize, FLASH_SMEM);

    // 1) prep
    prep_kernel<<<(CCH*CCH+255)/256, 256>>>(dgw1, wk, wv, bk, bv, w1sb, wkv, bkv);

    // 2) gram[b] = x^T x (tf32 mma, triangular + mirror); diag -> xx
    gram_mma<<<dim3(NTRI2, 1, BSZ), 256>>>(x, gram, xx);

    // 3) top-9
    topk_kernel<<<dim3(NPT, BSZ), 256>>>(gram, xx, idx);

    // 4) uv = [w1s; w1b] @ x
    gemm_mma<4><<<gmma64(2*CCH,NPT,BSZ), 128>>>(
        w1sb, x, uv, 2*CCH, NPT, CCH, CCH, NPT, NPT,
        0, CN, 2*CN, nullptr, nullptr, nullptr, 0, nullptr, 0, 0);

    // 5) edge features -> h
    {
        long long total = (long long)BSZ*CNK;
        gather_h_kernel<<<(unsigned)((total+255)/256), 256>>>(uv, idx, dgb1, dgg1, dgbe1, h);
    }

    // 6) conv2 + bn + relu + max-over-k fused -> agg + cat
    conv2max_mma<<<dim3(C2_NCOLS/C2_TN, 1, BSZ), 256>>>(
        dgw2, h, dgb2, dgg2, dgbe2, agg, cat);

    // 7) q, kv projections
    gemm_mma<4><<<gmma64(CCH,NPT,BSZ), 128>>>(
        wq, agg, q, CCH, NPT, CCH, CCH, NPT, NPT,
        0, CN, CN, bq, nullptr, nullptr, 0, nullptr, 0, 0);
    gemm_mma<4><<<gmma64(2*CCH,NPT,BSZ), 128>>>(
        wkv, y, kvb, 2*CCH, NPT, CCH, CCH, NPT, NPT,
        0, CN, 2*CN, bkv, nullptr, nullptr, 0, nullptr, 0, 0);

    // 8) fused attention (tf32 mma, cp.async K/V pipeline) -> add
    {
        dim3 grid((NPT + FQT - 1)/FQT, NHEAD, BSZ);
        flash_mma<<<grid, 256, FLASH_SMEM>>>(q, kvb, add);
    }

    // 9) mh conv -> bottom half of cat
    gemm_mma<4><<<gmma64(CCH,NPT,BSZ), 128>>>(
        wmh, add, cat + CN, CCH, NPT, CCH, CCH, NPT, NPT,
        0, CN, 2*CN, bmh, nullptr, nullptr, 0, nullptr, 0, 0);

    // 10) hc = relu(bn(wc1 @ cat + bc1))
    gemm_mma<4><<<gmma64(2*CCH,NPT,BSZ), 128>>>(
        wc1, cat, hc, 2*CCH, NPT, 2*CCH, 2*CCH, NPT, NPT,
        0, 2*CN, 2*CN, bc1, cg, cbe, 1, nullptr, 0, 0);

    // 11) out = agg + wc2 @ hc + bc2
    gemm_mma<4><<<gmma64(CCH,NPT,BSZ), 128>>>(
        wc2, hc, out, CCH, NPT, 2*CCH, 2*CCH, NPT, NPT,
        0, 2*CN, CN, bc2, nullptr, nullptr, 0, agg, CN, NPT);
}

// round 17
// speedup vs baseline: 1.0088x; 1.0088x over previous
#include <cuda_runtime.h>
#include <math.h>
#include <stdint.h>

#define BSZ   4
#define CCH   128
#define NPT   2000
#define KNNK  9
#define NHEAD 4
#define HD    32
#define BN_EPS 1e-5f

// ---------------- scratch ------------------------------------------------
__device__ float g_w1sb[2*CCH*CCH];
__device__ float g_wkv [2*CCH*CCH];
__device__ float g_bkv [2*CCH];
__device__ float g_gram[(size_t)BSZ*NPT*NPT];
__device__ float g_xx[BSZ*NPT];
__device__ int   g_idx[BSZ*NPT*KNNK];
__device__ float g_uv[BSZ*2*CCH*NPT];
__device__ float g_h [(size_t)BSZ*CCH*NPT*KNNK];
__device__ float g_agg[BSZ*CCH*NPT];
__device__ float g_q  [BSZ*CCH*NPT];
__device__ float g_kv [BSZ*2*CCH*NPT];
__device__ float g_add[BSZ*CCH*NPT];
__device__ float g_cat[BSZ*2*CCH*NPT];
__device__ float g_hc [BSZ*2*CCH*NPT];

// ---------------- tf32 helpers -------------------------------------------
__device__ __forceinline__ uint32_t f2tf32(float x){
    uint32_t r;
    asm("cvt.rna.tf32.f32 %0, %1;" : "=r"(r) : "f"(x));
    return r;
}
__device__ __forceinline__ void mma_tf32(float* d, const uint32_t* a, uint32_t b0, uint32_t b1){
    asm volatile(
        "mma.sync.aligned.m16n8k8.row.col.f32.tf32.tf32.f32 "
        "{%0,%1,%2,%3},{%4,%5,%6,%7},{%8,%9},{%0,%1,%2,%3};"
        : "+f"(d[0]), "+f"(d[1]), "+f"(d[2]), "+f"(d[3])
        : "r"(a[0]), "r"(a[1]), "r"(a[2]), "r"(a[3]), "r"(b0), "r"(b1));
}
__device__ __forceinline__ void cp_async16(uint32_t saddr, const float* g, bool pred){
    asm volatile("cp.async.cg.shared.global [%0], [%1], 16, %2;"
        :: "r"(saddr), "l"(g), "r"(pred ? 16 : 0));
}
__device__ __forceinline__ void split_tf32(float x, uint32_t& hi, uint32_t& lo){
    hi = f2tf32(x);
    lo = f2tf32(x - __uint_as_float(hi));
}

// ---------------- split-tf32 MMA GEMM, cp.async double-buffered (R11) --------
#define GM_TN 64
#define GA_LD 20
#define GB_LD 72

template<int NW>
__global__ void __launch_bounds__(NW*32) gemm_mma(
    const float* __restrict__ A, const float* __restrict__ B, float* __restrict__ Cm,
    int M, int Nc, int Kc, int lda, int ldb, int ldc,
    long long sA, long long sB, long long sC,
    const float* __restrict__ bias,
    const float* __restrict__ gamma, const float* __restrict__ beta,
    int relu,
    const float* __restrict__ resid, long long sR, int ldr)
{
    constexpr int TMT = NW*16;
    constexpr int NTH = NW*32;
    constexpr int AIT = (TMT*4)/NTH;
    constexpr int BIT = 256/NTH;

    int bz = blockIdx.z;
    A  += (long long)bz * sA;
    B  += (long long)bz * sB;
    Cm += (long long)bz * sC;
    if (resid) resid += (long long)bz * sR;

    __shared__ float As[2][TMT*GA_LD];
    __shared__ float Bs[2][16*GB_LD];

    int m0 = blockIdx.y * TMT;
    int n0 = blockIdx.x * GM_TN;
    int tid = threadIdx.x;
    int w = tid >> 5, lane = tid & 31;
    int g = lane >> 2, t = lane & 3;
    int row = w*16;

    int a_k4 = tid & 3,  a_r  = tid >> 2;
    int b_n4 = tid & 15, b_k  = tid >> 4;

    float acc[8][4];
    #pragma unroll
    for (int i=0;i<8;i++)
        #pragma unroll
        for (int j=0;j<4;j++) acc[i][j] = 0.f;

#define GMM_PREFETCH(KC, BUF) {                                              \
    _Pragma("unroll")                                                        \
    for (int it=0; it<AIT; it++){                                            \
        int r = a_r + it*(NTH/4);                                            \
        int gm = m0 + r;                                                     \
        uint32_t sa = (uint32_t)__cvta_generic_to_shared(                    \
            &As[BUF][r*GA_LD + a_k4*4]);                                     \
        cp_async16(sa, A + (long long)gm*lda + (KC) + a_k4*4, gm < M);       \
    }                                                                        \
    _Pragma("unroll")                                                        \
    for (int it=0; it<BIT; it++){                                            \
        int k_ = b_k + it*(NTH/16);                                          \
        int gn = n0 + b_n4*4;                                                \
        uint32_t sb = (uint32_t)__cvta_generic_to_shared(                    \
            &Bs[BUF][k_*GB_LD + b_n4*4]);                                    \
        cp_async16(sb, B + (long long)((KC) + k_)*ldb + gn, gn < Nc);        \
    }                                                                        \
    asm volatile("cp.async.commit_group;" ::: "memory"); }

#define GMM_COMPUTE(BUF) {                                                   \
    _Pragma("unroll")                                                        \
    for (int ks=0; ks<2; ks++){                                              \
        int c0 = ks*8;                                                       \
        uint32_t ah[4], al[4];                                               \
        {                                                                    \
            float a0 = As[BUF][(row+g  )*GA_LD + c0 + t];                    \
            float a1 = As[BUF][(row+8+g)*GA_LD + c0 + t];                    \
            float a2 = As[BUF][(row+g  )*GA_LD + c0 + t + 4];                \
            float a3 = As[BUF][(row+8+g)*GA_LD + c0 + t + 4];                \
            split_tf32(a0, ah[0], al[0]);                                    \
            split_tf32(a1, ah[1], al[1]);                                    \
            split_tf32(a2, ah[2], al[2]);                                    \
            split_tf32(a3, ah[3], al[3]);                                    \
        }                                                                    \
        int kr = ks*8 + t;                                                   \
        _Pragma("unroll")                                                    \
        for (int nt=0; nt<8; nt++){                                          \
            int cidx = nt*8 + g;                                             \
            float b0 = Bs[BUF][(kr  )*GB_LD + cidx];                         \
            float b1 = Bs[BUF][(kr+4)*GB_LD + cidx];                         \
            uint32_t bh0, bl0, bh1, bl1;                                     \
            split_tf32(b0, bh0, bl0);                                        \
            split_tf32(b1, bh1, bl1);                                        \
            mma_tf32(acc[nt], ah, bh0, bh1);                                 \
            mma_tf32(acc[nt], ah, bl0, bl1);                                 \
            mma_tf32(acc[nt], al, bh0, bh1);                                 \
        }                                                                    \
    } }

    const int NC = Kc >> 4;
    GMM_PREFETCH(0, 0);
    int buf = 0;
    for (int c = 0; c < NC; c++){
        if (c + 1 < NC){
            GMM_PREFETCH((c+1)*16, buf^1);
            asm volatile("cp.async.wait_group 1;" ::: "memory");
        } else {
            asm volatile("cp.async.wait_group 0;" ::: "memory");
        }
        __syncthreads();
        GMM_COMPUTE(buf);
        __syncthreads();
        buf ^= 1;
    }

    const float invs = rsqrtf(1.0f + BN_EPS);
    #pragma unroll
    for (int half=0; half<2; half++){
        int gm = m0 + row + half*8 + g;
        if (gm >= M) continue;
        float bi = bias  ? bias[gm]       : 0.f;
        float ga = gamma ? gamma[gm]*invs : 1.f;
        float be = beta  ? beta[gm]       : 0.f;
        #pragma unroll
        for (int nt=0; nt<8; nt++){
            int c0 = n0 + nt*8 + 2*t;
            #pragma unroll
            for (int jj=0; jj<2; jj++){
                int gn = c0 + jj;
                if (gn >= Nc) continue;
                float r = acc[nt][half*2 + jj] + bi;
                if (gamma) r = r*ga + be;
                if (relu)  r = fmaxf(r, 0.f);
                if (resid) r += resid[(long long)gm*ldr + gn];
                Cm[(long long)gm*ldc + gn] = r;
            }
        }
    }
#undef GMM_PREFETCH
#undef GMM_COMPUTE
}

// ---------------- dual GEMM: uv + kv in one launch ---------------------------
// z in [0, 2*BSZ): z<BSZ -> uv = w1sb @ x[b]; else kv = wkv @ y[b] + bkv.
// Same pipeline as gemm_mma<4>, M=256, K=128, N=NPT fixed.
__global__ void __launch_bounds__(128) gemm_uvkv_mma(
    const float* __restrict__ w1sb, const float* __restrict__ x,
    const float* __restrict__ wkv,  const float* __restrict__ y,
    const float* __restrict__ bkv,
    float* __restrict__ uv, float* __restrict__ kvb)
{
    constexpr int TMT = 64;
    constexpr int NTH = 128;

    int z = blockIdx.z;
    int sel = (z >= BSZ);
    int b = sel ? (z - BSZ) : z;
    const float* A = sel ? wkv : w1sb;
    const float* B = (sel ? y : x) + (long long)b*CCH*NPT;
    float* Cm = (sel ? kvb : uv) + (long long)b*2*CCH*NPT;
    const float* bias = sel ? bkv : nullptr;
    const int M = 2*CCH, Nc = NPT, lda = CCH, ldb = NPT, ldc = NPT;

    __shared__ float As[2][TMT*GA_LD];
    __shared__ float Bs[2][16*GB_LD];

    int m0 = blockIdx.y * TMT;
    int n0 = blockIdx.x * GM_TN;
    int tid = threadIdx.x;
    int w = tid >> 5, lane = tid & 31;
    int g = lane >> 2, t = lane & 3;
    int row = w*16;

    int a_k4 = tid & 3,  a_r  = tid >> 2;
    int b_n4 = tid & 15, b_k  = tid >> 4;

    float acc[8][4];
    #pragma unroll
    for (int i=0;i<8;i++)
        #pragma unroll
        for (int j=0;j<4;j++) acc[i][j] = 0.f;

#define DU_PREFETCH(KC, BUF) {                                               \
    _Pragma("unroll")                                                        \
    for (int it=0; it<2; it++){                                              \
        int r = a_r + it*(NTH/4);                                            \
        int gm = m0 + r;                                                     \
        uint32_t sa = (uint32_t)__cvta_generic_to_shared(                    \
            &As[BUF][r*GA_LD + a_k4*4]);                                     \
        cp_async16(sa, A + (long long)gm*lda + (KC) + a_k4*4, gm < M);       \
    }                                                                        \
    _Pragma("unroll")                                                        \
    for (int it=0; it<2; it++){                                              \
        int k_ = b_k + it*(NTH/16);                                          \
        int gn = n0 + b_n4*4;                                                \
        uint32_t sb = (uint32_t)__cvta_generic_to_shared(                    \
            &Bs[BUF][k_*GB_LD + b_n4*4]);                                    \
        cp_async16(sb, B + (long long)((KC) + k_)*ldb + gn, gn < Nc);        \
    }                                                                        \
    asm volatile("cp.async.commit_group;" ::: "memory"); }

#define DU_COMPUTE(BUF) {                                                    \
    _Pragma("unroll")                                                        \
    for (int ks=0; ks<2; ks++){                                              \
        int c0 = ks*8;                                                       \
        uint32_t ah[4], al[4];                                               \
        {                                                                    \
            float a0 = As[BUF][(row+g  )*GA_LD + c0 + t];                    \
            float a1 = As[BUF][(row+8+g)*GA_LD + c0 + t];                    \
            float a2 = As[BUF][(row+g  )*GA_LD + c0 + t + 4];                \
            float a3 = As[BUF][(row+8+g)*GA_LD + c0 + t + 4];                \
            split_tf32(a0, ah[0], al[0]);                                    \
            split_tf32(a1, ah[1], al[1]);                                    \
            split_tf32(a2, ah[2], al[2]);                                    \
            split_tf32(a3, ah[3], al[3]);                                    \
        }                                                                    \
        int kr = ks*8 + t;                                                   \
        _Pragma("unroll")                                                    \
        for (int nt=0; nt<8; nt++){                                          \
            int cidx = nt*8 + g;                                             \
            float b0 = Bs[BUF][(kr  )*GB_LD + cidx];                         \
            float b1 = Bs[BUF][(kr+4)*GB_LD + cidx];                         \
            uint32_t bh0, bl0, bh1, bl1;                                     \
            split_tf32(b0, bh0, bl0);                                        \
            split_tf32(b1, bh1, bl1);                                        \
            mma_tf32(acc[nt], ah, bh0, bh1);                                 \
            mma_tf32(acc[nt], ah, bl0, bl1);                                 \
            mma_tf32(acc[nt], al, bh0, bh1);                                 \
        }                                                                    \
    } }

    const int NC = CCH >> 4;   // 8
    DU_PREFETCH(0, 0);
    int buf = 0;
    for (int c = 0; c < NC; c++){
        if (c + 1 < NC){
            DU_PREFETCH((c+1)*16, buf^1);
            asm volatile("cp.async.wait_group 1;" ::: "memory");
        } else {
            asm volatile("cp.async.wait_group 0;" ::: "memory");
        }
        __syncthreads();
        DU_COMPUTE(buf);
        __syncthreads();
        buf ^= 1;
    }

    #pragma unroll
    for (int half=0; half<2; half++){
        int gm = m0 + row + half*8 + g;
        if (gm >= M) continue;
        float bi = bias ? bias[gm] : 0.f;
        #pragma unroll
        for (int nt=0; nt<8; nt++){
            int c0 = n0 + nt*8 + 2*t;
            #pragma unroll
            for (int jj=0; jj<2; jj++){
                int gn = c0 + jj;
                if (gn >= Nc) continue;
                Cm[(long long)gm*ldc + gn] = acc[nt][half*2 + jj] + bi;
            }
        }
    }
#undef DU_PREFETCH
#undef DU_COMPUTE
}

// ---------------- conv2 + max-over-k fused (R13 proven) --------------------
#define C2_TN 72
#define C2_SLD 76
#define C2_NCOLS (NPT*KNNK)

__global__ void __launch_bounds__(256) conv2max_mma(
    const float* __restrict__ W,
    const float* __restrict__ hsrc,
    const float* __restrict__ bias, const float* __restrict__ gamma,
    const float* __restrict__ beta,
    float* __restrict__ agg,
    float* __restrict__ cat)
{
    __shared__ float SM[CCH*C2_SLD];
    float* ASb = SM;
    float* BSb = SM + 2*CCH*GA_LD;
#define C2_AS(BUF) (ASb + (BUF)*CCH*GA_LD)
#define C2_BS(BUF) (BSb + (BUF)*16*C2_TN)

    int b = blockIdx.z;
    const float* Bsrc = hsrc + (long long)b*CCH*C2_NCOLS;
    int n0 = blockIdx.x * C2_TN;
    int tid = threadIdx.x;
    int w = tid >> 5, lane = tid & 31;
    int g = lane >> 2, t = lane & 3;
    int row = w*16;
    int a_k4 = tid & 3, a_r = tid >> 2;

    float acc[9][4];
    #pragma unroll
    for (int i=0;i<9;i++)
        #pragma unroll
        for (int j=0;j<4;j++) acc[i][j] = 0.f;

#define C2_PREFETCH(KC, BUF) {                                               \
    _Pragma("unroll")                                                        \
    for (int it=0; it<2; it++){                                              \
        int r = a_r + it*64;                                                 \
        uint32_t sa = (uint32_t)__cvta_generic_to_shared(                    \
            &C2_AS(BUF)[r*GA_LD + a_k4*4]);                                  \
        cp_async16(sa, W + (long long)r*CCH + (KC) + a_k4*4, true);          \
    }                                                                        \
    _Pragma("unroll")                                                        \
    for (int it=0; it<2; it++){                                              \
        int e = tid + it*256;                                                \
        if (e < 288){                                                        \
            int k_ = e/18, n4 = e%18;                                        \
            uint32_t sb = (uint32_t)__cvta_generic_to_shared(                \
                &C2_BS(BUF)[k_*C2_TN + n4*4]);                               \
            cp_async16(sb, Bsrc + (long long)((KC)+k_)*C2_NCOLS + n0 + n4*4, true); \
        }                                                                    \
    }                                                                        \
    asm volatile("cp.async.commit_group;" ::: "memory"); }

#define C2_COMPUTE(BUF) {                                                    \
    _Pragma("unroll")                                                        \
    for (int ks=0; ks<2; ks++){                                              \
        int c0 = ks*8;                                                       \
        uint32_t ah[4], al[4];                                               \
        {                                                                    \
            float a0 = C2_AS(BUF)[(row+g  )*GA_LD + c0 + t];                 \
            float a1 = C2_AS(BUF)[(row+8+g)*GA_LD + c0 + t];                 \
            float a2 = C2_AS(BUF)[(row+g  )*GA_LD + c0 + t + 4];             \
            float a3 = C2_AS(BUF)[(row+8+g)*GA_LD + c0 + t + 4];             \
            split_tf32(a0, ah[0], al[0]);                                    \
            split_tf32(a1, ah[1], al[1]);                                    \
            split_tf32(a2, ah[2], al[2]);                                    \
            split_tf32(a3, ah[3], al[3]);                                    \
        }                                                                    \
        int kr = ks*8 + t;                                                   \
        _Pragma("unroll")                                                    \
        for (int nt=0; nt<9; nt++){                                          \
            int cidx = nt*8 + g;                                             \
            float b0 = C2_BS(BUF)[(kr  )*C2_TN + cidx];                      \
            float b1 = C2_BS(BUF)[(kr+4)*C2_TN + cidx];                      \
            uint32_t bh0, bl0, bh1, bl1;                                     \
            split_tf32(b0, bh0, bl0);                                        \
            split_tf32(b1, bh1, bl1);                                        \
            mma_tf32(acc[nt], ah, bh0, bh1);                                 \
            mma_tf32(acc[nt], ah, bl0, bl1);                                 \
            mma_tf32(acc[nt], al, bh0, bh1);                                 \
        }                                                                    \
    } }

    const int NC = CCH >> 4;
    C2_PREFETCH(0, 0);
    int buf = 0;
    for (int c = 0; c < NC; c++){
        if (c + 1 < NC){
            C2_PREFETCH((c+1)*16, buf^1);
            asm volatile("cp.async.wait_group 1;" ::: "memory");
        } else {
            asm volatile("cp.async.wait_group 0;" ::: "memory");
        }
        __syncthreads();
        C2_COMPUTE(buf);
        __syncthreads();
        buf ^= 1;
    }

    const float invs = rsqrtf(1.0f + BN_EPS);
    #pragma unroll
    for (int half=0; half<2; half++){
        int r = row + half*8 + g;
        float bi = bias[r];
        float ga = gamma[r]*invs;
        float be = beta[r];
        #pragma unroll
        for (int nt=0; nt<9; nt++){
            #pragma unroll
            for (int jj=0; jj<2; jj++){
                int c = nt*8 + 2*t + jj;
                float v = fmaxf((acc[nt][half*2 + jj] + bi)*ga + be, 0.f);
                SM[r*C2_SLD + c] = v;
            }
        }
    }
    __syncthreads();

    #pragma unroll
    for (int e = tid; e < CCH*8; e += 256){
        int r = e >> 3, gi = e & 7;
        int n = 8*blockIdx.x + gi;
        const float* p = &SM[r*C2_SLD + gi*9];
        float m = p[0];
        #pragma unroll
        for (int k=1;k<9;k++) m = fmaxf(m, p[k]);
        agg[((long long)b*CCH + r)*NPT + n] = m;
        cat[(long long)b*2*CCH*NPT + (long long)r*NPT + n] = m;
    }
#undef C2_PREFETCH
#undef C2_COMPUTE
#undef C2_AS
#undef C2_BS
}

// ---------------- Gram via split-tf32 MMA (R9 proven) ------------------------
#define GM_TM 128
#define GRA_LD 17

__global__ void __launch_bounds__(256) gram_mma(
    const float* __restrict__ x,
    float* __restrict__ gram,
    float* __restrict__ xx)
{
    __shared__ float AH[GM_TM*GRA_LD], AL[GM_TM*GRA_LD];
    __shared__ float BH[16*GB_LD],    BL[16*GB_LD];

    int b = blockIdx.z;
    const float* xb = x + (long long)b*CCH*NPT;
    float* gb = gram + (long long)b*NPT*NPT;

    int tt = blockIdx.x;
    int bi = 0;
    while ((32*(bi+1) - (bi+1)*bi) <= tt) bi++;
    int bj2 = 2*bi + (tt - (32*bi - bi*(bi-1)));

    int m0 = bi * GM_TM;
    int n0 = bj2 * GM_TN;
    int tid = threadIdx.x;
    int w = tid >> 5, lane = tid & 31;
    int g = lane >> 2, t = lane & 3;
    int row = w*16;

    float acc[8][4];
    #pragma unroll
    for (int i=0;i<8;i++)
        #pragma unroll
        for (int j=0;j<4;j++) acc[i][j] = 0.f;

    for (int kc = 0; kc < CCH; kc += 16) {
        #pragma unroll
        for (int it=0; it<8; it++){
            int e = tid + it*256;
            int r = e & 127, kk = e >> 7;
            int gm = m0 + r;
            float av = (gm < NPT) ? xb[(long long)(kc+kk)*NPT + gm] : 0.f;
            float ah = __uint_as_float(f2tf32(av));
            AH[r*GRA_LD + kk] = ah;
            AL[r*GRA_LD + kk] = __uint_as_float(f2tf32(av - ah));
        }
        #pragma unroll
        for (int it=0; it<4; it++){
            int e = tid + it*256;
            int n_ = e & 63, k_ = e >> 6;
            int gn = n0 + n_;
            float bv = (gn < NPT) ? xb[(long long)(kc + k_)*NPT + gn] : 0.f;
            float bh = __uint_as_float(f2tf32(bv));
            BH[k_*GB_LD + n_] = bh;
            BL[k_*GB_LD + n_] = __uint_as_float(f2tf32(bv - bh));
        }
        __syncthreads();

        #pragma unroll
        for (int ks=0; ks<2; ks++){
            int c0 = ks*8;
            uint32_t ah[4], al[4];
            ah[0] = __float_as_uint(AH[(row+g  )*GRA_LD + c0 + t]);
            ah[1] = __float_as_uint(AH[(row+8+g)*GRA_LD + c0 + t]);
            ah[2] = __float_as_uint(AH[(row+g  )*GRA_LD + c0 + t + 4]);
            ah[3] = __float_as_uint(AH[(row+8+g)*GRA_LD + c0 + t + 4]);
            al[0] = __float_as_uint(AL[(row+g  )*GRA_LD + c0 + t]);
            al[1] = __float_as_uint(AL[(row+8+g)*GRA_LD + c0 + t]);
            al[2] = __float_as_uint(AL[(row+g  )*GRA_LD + c0 + t + 4]);
            al[3] = __float_as_uint(AL[(row+8+g)*GRA_LD + c0 + t + 4]);
            int kr = ks*8 + t;
            #pragma unroll
            for (int nt=0; nt<8; nt++){
                int cidx = nt*8 + g;
                uint32_t bh0 = __float_as_uint(BH[(kr  )*GB_LD + cidx]);
                uint32_t bh1 = __float_as_uint(BH[(kr+4)*GB_LD + cidx]);
                uint32_t bl0 = __float_as_uint(BL[(kr  )*GB_LD + cidx]);
                uint32_t bl1 = __float_as_uint(BL[(kr+4)*GB_LD + cidx]);
                mma_tf32(acc[nt], ah, bh0, bh1);
                mma_tf32(acc[nt], ah, bl0, bl1);
                mma_tf32(acc[nt], al, bh0, bh1);
            }
        }
        __syncthreads();
    }

    bool diagtile = (bj2 >> 1) == bi;
    #pragma unroll
    for (int half=0; half<2; half++){
        int gm = m0 + row + half*8 + g;
        if (gm >= NPT) continue;
        #pragma unroll
        for (int nt=0; nt<8; nt++){
            #pragma unroll
            for (int jj=0; jj<2; jj++){
                int gn = n0 + nt*8 + 2*t + jj;
                if (gn >= NPT) continue;
                float val = acc[nt][half*2 + jj];
                gb[(long long)gm*NPT + gn] = val;
                gb[(long long)gn*NPT + gm] = val;
                if (diagtile && gm == gn) xx[b*NPT + gm] = val;
            }
        }
    }
}

// ---------------- prep ------------------------------------------------------
__global__ void prep_kernel(const float* __restrict__ w1,
                            const float* __restrict__ wk, const float* __restrict__ wv,
                            const float* __restrict__ bk, const float* __restrict__ bv,
                            float* __restrict__ w1sb, float* __restrict__ wkv,
                            float* __restrict__ bkv)
{
    int i = blockIdx.x*blockDim.x + threadIdx.x;
    if (i < CCH*CCH) {
        int o = i / CCH, c = i % CCH;
        float a  = w1[o*2*CCH + c];
        float bb = w1[o*2*CCH + CCH + c];
        w1sb[i] = a + bb;
        w1sb[CCH*CCH + i] = bb;
        wkv[i] = wk[i];
        wkv[CCH*CCH + i] = wv[i];
    }
    if (i < 2*CCH) bkv[i] = (i < CCH) ? bk[i] : bv[i - CCH];
}

// ---------------- topk: lane sort-8 + warp k-way merge -----------------------
__global__ void __launch_bounds__(256) topk_kernel(const float* __restrict__ gram,
                                                   const float* __restrict__ xx,
                                                   int* __restrict__ idx)
{
    int n = blockIdx.x, b = blockIdx.y;
    const float* row = gram + ((long long)(b*NPT+n))*NPT;
    const float* xb  = xx + b*NPT;
    int tid = threadIdx.x, w = tid >> 5, l = tid & 31;

    float v[8]; int id[8];
    #pragma unroll
    for (int j=0;j<8;j++){
        int m = w*256 + j*32 + l;
        bool ok = m < NPT;
        v[j]  = ok ? (2.f*row[m] - xb[m]) : -INFINITY;
        id[j] = ok ? m : 0x7fffffff;
    }
#define CSWP(a,bb) { bool sw = (v[a]<v[bb]) || (v[a]==v[bb] && id[a]>id[bb]); \
    float tv = sw?v[bb]:v[a]; float uv2 = sw?v[a]:v[bb]; v[a]=tv; v[bb]=uv2;   \
    int ti = sw?id[bb]:id[a]; int ui = sw?id[a]:id[bb]; id[a]=ti; id[bb]=ui; }
    CSWP(0,1) CSWP(2,3) CSWP(4,5) CSWP(6,7)
    CSWP(0,2) CSWP(1,3) CSWP(4,6) CSWP(5,7)
    CSWP(1,2) CSWP(5,6)
    CSWP(0,4) CSWP(1,5) CSWP(2,6) CSWP(3,7)
    CSWP(2,4) CSWP(3,5)
    CSWP(1,2) CSWP(3,4) CSWP(5,6)
#undef CSWP

    __shared__ float wv[8][12];
    __shared__ int   wi[8][12];

    float hv = v[0]; int hi = id[0];
    #pragma unroll
    for (int t=0;t<KNNK;t++){
        float bvv = hv; int bii = hi;
        #pragma unroll
        for (int s=16; s>0; s>>=1){
            float ov = __shfl_xor_sync(0xffffffffu, bvv, s);
            int   oi = __shfl_xor_sync(0xffffffffu, bii, s);
            if (ov > bvv || (ov == bvv && oi < bii)) { bvv = ov; bii = oi; }
        }
        if (l == 0) { wv[w][t] = bvv; wi[w][t] = bii; }
        if (hi == bii) {
            #pragma unroll
            for (int j=0;j<7;j++){ v[j]=v[j+1]; id[j]=id[j+1]; }
            v[7] = -INFINITY; id[7] = 0x7fffffff;
            hv = v[0]; hi = id[0];
        }
    }
    __syncthreads();

    if (w == 0){
        int ptr = 0;
        float hv2 = (l < 8) ? wv[l][0] : -INFINITY;
        int   hi2 = (l < 8) ? wi[l][0] : 0x7fffffff;
        int* outp = idx + (b*NPT+n)*KNNK;
        #pragma unroll
        for (int t=0;t<KNNK;t++){
            float bvv = hv2; int bii = hi2;
            #pragma unroll
            for (int s=16; s>0; s>>=1){
                float ov = __shfl_xor_sync(0xffffffffu, bvv, s);
                int   oi = __shfl_xor_sync(0xffffffffu, bii, s);
                if (ov > bvv || (ov == bvv && oi < bii)) { bvv = ov; bii = oi; }
            }
            if (l == 0) outp[t] = bii;
            if (hi2 == bii){
                ptr++;
                hv2 = (ptr < KNNK && l < 8) ? wv[l][ptr] : -INFINITY;
                hi2 = (ptr < KNNK && l < 8) ? wi[l][ptr] : 0x7fffffff;
            }
        }
    }
}

// h[b,c,n*9+k] = relu( bn( u[b,c,n] - v[b,c,idx] + b1[c] ) )
__global__ void gather_h_kernel(const float* __restrict__ uv,
                                const int* __restrict__ idx,
                                const float* __restrict__ b1, const float* __restrict__ g1,
                                const float* __restrict__ be1, float* __restrict__ h)
{
    long long i = (long long)blockIdx.x*blockDim.x + threadIdx.x;
    const long long total = (long long)BSZ*CCH*NPT*KNNK;
    if (i >= total) return;
    int k = (int)(i % KNNK);
    long long r = i / KNNK;
    int n = (int)(r % NPT); r /= NPT;
    int c = (int)(r % CCH);
    int b = (int)(r / CCH);
    int j = idx[(b*NPT+n)*KNNK + k];
    const float* ub = uv + (long long)b*2*CCH*NPT + (long long)c*NPT;
    float uvv = ub[n];
    float vg  = ub[(long long)CCH*NPT + j];
    const float invs = rsqrtf(1.f + BN_EPS);
    float val = (uvv - vg + b1[c]) * (g1[c]*invs) + be1[c];
    h[((long long)(b*CCH+c))*NPT*KNNK + (long long)n*KNNK + k] = fmaxf(val, 0.f);
}

// ---------------- flash attention with tf32 mma.sync (R15 proven) -------------
#define FQT 128
#define FKT 64
#define QS_LD 36
#define KD_LD 72
#define VT_LD2 40
#define OF_QH 0
#define OF_QL (FQT*QS_LD)
#define OF_KH (OF_QL + FQT*QS_LD)
#define OF_KL (OF_KH + HD*KD_LD)
#define OF_VT (OF_KL + HD*KD_LD)
#define FLASH_SM_FLOATS (OF_VT + FKT*VT_LD2)

__global__ void __launch_bounds__(256,2) flash_mma(
    const float* __restrict__ q,
    const float* __restrict__ kv,
    float* __restrict__ add)
{
    extern __shared__ float sm[];
    float* Qsh = sm + OF_QH;
    float* Qsl = sm + OF_QL;
    float* Kdh = sm + OF_KH;
    float* Kdl = sm + OF_KL;
    float* Vt  = sm + OF_VT;

    int n0 = blockIdx.x * FQT;
    int h  = blockIdx.y;
    int b  = blockIdx.z;
    const float* qp = q  + ((long long)b*CCH   + h*HD)*NPT;
    const float* kp = kv + ((long long)b*2*CCH + h*HD)*NPT;
    const float* vp = kv + ((long long)b*2*CCH + CCH + h*HD)*NPT;
    float* oh = add + ((long long)b*CCH + h*HD)*NPT;

    int tid = threadIdx.x;
    const float scale = 0.17677669529663689f;

    #pragma unroll
    for (int e = tid; e < FQT*HD; e += 256) {
        int d = e >> 7, r = e & 127;
        int n = n0 + r;
        float qv = (n < NPT) ? qp[d*NPT + n]*scale : 0.f;
        float hf = __uint_as_float(f2tf32(qv));
        Qsh[r*QS_LD + d] = hf;
        Qsl[r*QS_LD + d] = __uint_as_float(f2tf32(qv - hf));
    }

    int w = tid >> 5, lane = tid & 31;
    int g = lane >> 2, t = lane & 3;
    int row = w*16 + g;

    float O[4][4];
    #pragma unroll
    for (int i=0;i<4;i++)
        #pragma unroll
        for (int j=0;j<4;j++) O[i][j] = 0.f;
    float m0r = -INFINITY, m1r = -INFINITY, l0r = 0.f, l1r = 0.f;

    const int NT = (NPT + FKT - 1)/FKT;

    for (int ti = 0; ti < NT; ti++) {
        int m0 = ti*FKT;
        __syncthreads();
        #pragma unroll
        for (int e = tid; e < HD*FKT; e += 256) {
            int d = e >> 6, c = e & 63;
            int m = m0 + c;
            float kvv = (m < NPT) ? kp[d*NPT + m] : 0.f;
            float hf = __uint_as_float(f2tf32(kvv));
            Kdh[d*KD_LD + c] = hf;
            Kdl[d*KD_LD + c] = __uint_as_float(f2tf32(kvv - hf));
            float vv = (m < NPT) ? vp[d*NPT + m] : 0.f;
            Vt[c*VT_LD2 + d] = __uint_as_float(f2tf32(vv));
        }
        __syncthreads();

        uint32_t qa[4][4], ql[4][4];
        #pragma unroll
        for (int ks=0; ks<4; ks++){
            int c0 = ks*8;
            qa[ks][0] = __float_as_uint(Qsh[(row  )*QS_LD + c0 + t]);
            qa[ks][1] = __float_as_uint(Qsh[(row+8)*QS_LD + c0 + t]);
            qa[ks][2] = __float_as_uint(Qsh[(row  )*QS_LD + c0 + t + 4]);
            qa[ks][3] = __float_as_uint(Qsh[(row+8)*QS_LD + c0 + t + 4]);
            ql[ks][0] = __float_as_uint(Qsl[(row  )*QS_LD + c0 + t]);
            ql[ks][1] = __float_as_uint(Qsl[(row+8)*QS_LD + c0 + t]);
            ql[ks][2] = __float_as_uint(Qsl[(row  )*QS_LD + c0 + t + 4]);
            ql[ks][3] = __float_as_uint(Qsl[(row+8)*QS_LD + c0 + t + 4]);
        }

        float S[8][4];
        #pragma unroll
        for (int nt=0; nt<8; nt++){
            S[nt][0]=0.f; S[nt][1]=0.f; S[nt][2]=0.f; S[nt][3]=0.f;
            #pragma unroll
            for (int ks=0; ks<4; ks++){
                int kr = ks*8 + t;
                int cidx = nt*8 + g;
                uint32_t bh0 = __float_as_uint(Kdh[(kr  )*KD_LD + cidx]);
                uint32_t bh1 = __float_as_uint(Kdh[(kr+4)*KD_LD + cidx]);
                uint32_t bl0 = __float_as_uint(Kdl[(kr  )*KD_LD + cidx]);
                uint32_t bl1 = __float_as_uint(Kdl[(kr+4)*KD_LD + cidx]);
                mma_tf32(S[nt], qa[ks], bh0, bh1);
                mma_tf32(S[nt], qa[ks], bl0, bl1);
                mma_tf32(S[nt], ql[ks], bh0, bh1);
            }
        }

        int mval = NPT - m0;
        float lm0 = -INFINITY, lm1 = -INFINITY;
        #pragma unroll
        for (int nt=0; nt<8; nt++){
            int c0 = nt*8 + 2*t, c1 = c0 + 1;
            if (c0 < mval){ lm0 = fmaxf(lm0, S[nt][0]); lm1 = fmaxf(lm1, S[nt][2]); }
            if (c1 < mval){ lm0 = fmaxf(lm0, S[nt][1]); lm1 = fmaxf(lm1, S[nt][3]); }
        }
        lm0 = fmaxf(lm0, __shfl_xor_sync(0xffffffffu, lm0, 1));
        lm0 = fmaxf(lm0, __shfl_xor_sync(0xffffffffu, lm0, 2));
        lm1 = fmaxf(lm1, __shfl_xor_sync(0xffffffffu, lm1, 1));
        lm1 = fmaxf(lm1, __shfl_xor_sync(0xffffffffu, lm1, 2));

        float mn0 = fmaxf(m0r, lm0), mn1 = fmaxf(m1r, lm1);
        float al0 = __expf(m0r - mn0), al1 = __expf(m1r - mn1);
        m0r = mn0; m1r = mn1;

        float ls0 = 0.f, ls1 = 0.f;
        #pragma unroll
        for (int nt=0; nt<8; nt++){
            int c0 = nt*8 + 2*t, c1 = c0 + 1;
            float e0 = (c0 < mval) ? __expf(S[nt][0] - mn0) : 0.f;
            float e1 = (c1 < mval) ? __expf(S[nt][1] - mn0) : 0.f;
            float e2 = (c0 < mval) ? __expf(S[nt][2] - mn1) : 0.f;
            float e3 = (c1 < mval) ? __expf(S[nt][3] - mn1) : 0.f;
            S[nt][0]=e0; S[nt][1]=e1; S[nt][2]=e2; S[nt][3]=e3;
            ls0 += e0 + e1; ls1 += e2 + e3;
        }
        ls0 += __shfl_xor_sync(0xffffffffu, ls0, 1);
        ls0 += __shfl_xor_sync(0xffffffffu, ls0, 2);
        ls1 += __shfl_xor_sync(0xffffffffu, ls1, 1);
        ls1 += __shfl_xor_sync(0xffffffffu, ls1, 2);
        l0r = l0r*al0 + ls0;
        l1r = l1r*al1 + ls1;
        #pragma unroll
        for (int nd=0; nd<4; nd++){
            O[nd][0] *= al0; O[nd][1] *= al0;
            O[nd][2] *= al1; O[nd][3] *= al1;
        }

        int s1 = g*4 + (t>>1), s2 = s1 + 2;
        bool odd = (t & 1);
        #pragma unroll
        for (int kt2=0; kt2<8; kt2++){
            float x0 = __shfl_sync(0xffffffffu, S[kt2][0], s1);
            float x1 = __shfl_sync(0xffffffffu, S[kt2][1], s1);
            float x2 = __shfl_sync(0xffffffffu, S[kt2][2], s1);
            float x3 = __shfl_sync(0xffffffffu, S[kt2][3], s1);
            float y0 = __shfl_sync(0xffffffffu, S[kt2][0], s2);
            float y1 = __shfl_sync(0xffffffffu, S[kt2][1], s2);
            float y2 = __shfl_sync(0xffffffffu, S[kt2][2], s2);
            float y3 = __shfl_sync(0xffffffffu, S[kt2][3], s2);
            uint32_t pa[4];
            pa[0] = f2tf32(odd ? x1 : x0);
            pa[1] = f2tf32(odd ? x3 : x2);
            pa[2] = f2tf32(odd ? y1 : y0);
            pa[3] = f2tf32(odd ? y3 : y2);
            #pragma unroll
            for (int nd=0; nd<4; nd++){
                uint32_t b0 = __float_as_uint(Vt[(kt2*8 + t    )*VT_LD2 + nd*8 + g]);
                uint32_t b1 = __float_as_uint(Vt[(kt2*8 + t + 4)*VT_LD2 + nd*8 + g]);
                mma_tf32(O[nd], pa, b0, b1);
            }
        }
    }

    float inv0 = 1.f / l0r, inv1 = 1.f / l1r;
    int q0 = n0 + row, q1 = q0 + 8;
    #pragma unroll
    for (int nd=0; nd<4; nd++){
        int d0 = nd*8 + 2*t, d1 = d0 + 1;
        if (q0 < NPT){
            oh[(long long)d0*NPT + q0] = O[nd][0]*inv0;
            oh[(long long)d1*NPT + q0] = O[nd][1]*inv0;
        }
        if (q1 < NPT){
            oh[(long long)d0*NPT + q1] = O[nd][2]*inv1;
            oh[(long long)d1*NPT + q1] = O[nd][3]*inv1;
        }
    }
}

// ---------------- launch ------------------------------------------------------
static inline dim3 gmma64(int M, int Nc, int batches) {
    return dim3((Nc + GM_TN - 1)/GM_TN, (M + 63)/64, batches);
}

extern "C" void kernel_launch(void* const* d_in, const int* in_sizes, int n_in,
                              void* d_out, int out_size)
{
    const float* x    = (const float*)d_in[0];
    const float* y    = (const float*)d_in[1];
    const float* dgw1 = (const float*)d_in[2];
    const float* dgb1 = (const float*)d_in[3];
    const float* dgg1 = (const float*)d_in[4];
    const float* dgbe1= (const float*)d_in[5];
    const float* dgw2 = (const float*)d_in[6];
    const float* dgb2 = (const float*)d_in[7];
    const float* dgg2 = (const float*)d_in[8];
    const float* dgbe2= (const float*)d_in[9];
    const float* wq   = (const float*)d_in[10];
    const float* bq   = (const float*)d_in[11];
    const float* wk   = (const float*)d_in[12];
    const float* bk   = (const float*)d_in[13];
    const float* wv   = (const float*)d_in[14];
    const float* bv   = (const float*)d_in[15];
    const float* wmh  = (const float*)d_in[16];
    const float* bmh  = (const float*)d_in[17];
    const float* wc1  = (const float*)d_in[18];
    const float* bc1  = (const float*)d_in[19];
    const float* cg   = (const float*)d_in[20];
    const float* cbe  = (const float*)d_in[21];
    const float* wc2  = (const float*)d_in[22];
    const float* bc2  = (const float*)d_in[23];
    float* out = (float*)d_out;

    float *w1sb,*wkv,*bkv,*gram,*xx,*uv,*h,*agg,*q,*kvb,*add,*cat,*hc;
    int* idx;
    cudaGetSymbolAddress((void**)&w1sb, g_w1sb);
    cudaGetSymbolAddress((void**)&wkv,  g_wkv);
    cudaGetSymbolAddress((void**)&bkv,  g_bkv);
    cudaGetSymbolAddress((void**)&gram, g_gram);
    cudaGetSymbolAddress((void**)&xx,   g_xx);
    cudaGetSymbolAddress((void**)&idx,  g_idx);
    cudaGetSymbolAddress((void**)&uv,   g_uv);
    cudaGetSymbolAddress((void**)&h,    g_h);
    cudaGetSymbolAddress((void**)&agg,  g_agg);
    cudaGetSymbolAddress((void**)&q,    g_q);
    cudaGetSymbolAddress((void**)&kvb,  g_kv);
    cudaGetSymbolAddress((void**)&add,  g_add);
    cudaGetSymbolAddress((void**)&cat,  g_cat);
    cudaGetSymbolAddress((void**)&hc,   g_hc);

    const long long CN  = (long long)CCH*NPT;
    const long long CNK = (long long)CCH*NPT*KNNK;
    const int FLASH_SMEM = FLASH_SM_FLOATS * 4;
    const int NTRI2 = 272;

    cudaFuncSetAttribute(flash_mma, cudaFuncAttributeMaxDynamicSharedMemorySize, FLASH_SMEM);

    // 1) prep
    prep_kernel<<<(CCH*CCH+255)/256, 256>>>(dgw1, wk, wv, bk, bv, w1sb, wkv, bkv);

    // 2) gram[b] = x^T x (tf32 mma, triangular + mirror); diag -> xx
    gram_mma<<<dim3(NTRI2, 1, BSZ), 256>>>(x, gram, xx);

    // 3) top-9
    topk_kernel<<<dim3(NPT, BSZ), 256>>>(gram, xx, idx);

    // 4) uv = [w1s; w1b] @ x  AND  kv = [wk;wv]@y + [bk;bv]  (one dual launch)
    {
        dim3 grid((NPT + GM_TN - 1)/GM_TN, (2*CCH + 63)/64, 2*BSZ);
        gemm_uvkv_mma<<<grid, 128>>>(w1sb, x, wkv, y, bkv, uv, kvb);
    }

    // 5) edge features -> h
    {
        long long total = (long long)BSZ*CNK;
        gather_h_kernel<<<(unsigned)((total+255)/256), 256>>>(uv, idx, dgb1, dgg1, dgbe1, h);
    }

    // 6) conv2 + bn + relu + max-over-k fused -> agg + cat
    conv2max_mma<<<dim3(C2_NCOLS/C2_TN, 1, BSZ), 256>>>(
        dgw2, h, dgb2, dgg2, dgbe2, agg, cat);

    // 7) q projection
    gemm_mma<4><<<gmma64(CCH,NPT,BSZ), 128>>>(
        wq, agg, q, CCH, NPT, CCH, CCH, NPT, NPT,
        0, CN, CN, bq, nullptr, nullptr, 0, nullptr, 0, 0);

    // 8) fused attention (tf32 mma) -> add
    {
        dim3 grid((NPT + FQT - 1)/FQT, NHEAD, BSZ);
        flash_mma<<<grid, 256, FLASH_SMEM>>>(q, kvb, add);
    }

    // 9) mh conv -> bottom half of cat
    gemm_mma<4><<<gmma64(CCH,NPT,BSZ), 128>>>(
        wmh, add, cat + CN, CCH, NPT, CCH, CCH, NPT, NPT,
        0, CN, 2*CN, bmh, nullptr, nullptr, 0, nullptr, 0, 0);

    // 10) hc = relu(bn(wc1 @ cat + bc1))
    gemm_mma<4><<<gmma64(2*CCH,NPT,BSZ), 128>>>(
        wc1, cat, hc, 2*CCH, NPT, 2*CCH, 2*CCH, NPT, NPT,
        0, 2*CN, 2*CN, bc1, cg, cbe, 1, nullptr, 0, 0);

    // 11) out = agg + wc2 @ hc + bc2
    gemm_mma<4><<<gmma64(CCH,NPT,BSZ), 128>>>(
        wc2, hc, out, CCH, NPT, 2*CCH, 2*CCH, NPT, NPT,
        0, 2*CN, CN, bc2, nullptr, nullptr, 0, agg, CN, NPT);
}